// round 1
// baseline (speedup 1.0000x reference)
#include <cuda_runtime.h>

#define SEQLEN  512
#define T_TOT   513      // <SOS> + 512 teacher-forced tokens
#define EMB     256
#define HID     512
#define G4H     2048     // 4*HID
#define VOCAB   32000
#define NCTA    64       // recurrence CTAs (must all be co-resident; 64 <= 148 SMs)
#define SOS_ID  1

// ---------------- scratch (device globals; no allocation allowed) ----------------
__device__ float g_emb[T_TOT * EMB];     // gathered embeddings
__device__ float g_bias[G4H];            // b_ih + b_hh
__device__ float g_X[T_TOT * G4H];       // W_ih @ x_t + bias, all timesteps
__device__ float g_hs[T_TOT * HID];      // h_t for every step
__device__ int   g_cnt[T_TOT];           // per-step arrival counters (reset each launch)

// ---------------- K0: gather embeddings, combine biases, reset counters ----------
__global__ void setup_kernel(const int* __restrict__ seq,
                             const float* __restrict__ emb_table,
                             const float* __restrict__ b_ih,
                             const float* __restrict__ b_hh) {
    int b = blockIdx.x, t = threadIdx.x;   // blockDim == 256 == EMB
    if (b < T_TOT) {
        int tok = (b == 0) ? SOS_ID : seq[b - 1];
        g_emb[b * EMB + t] = emb_table[tok * EMB + t];
        if (t == 0) g_cnt[b] = 0;
    } else {
        int i = (b - T_TOT) * 256 + t;     // 8 blocks cover 2048
        g_bias[i] = b_ih[i] + b_hh[i];
    }
}

// ---------------- generic SGEMM: C[m][n] = sum_k A[m][k]*B[n][k] + bias[n] -------
// A: [M,K] row-major (M may be ragged, guarded). B: [N,K] row-major, N%128==0, K%8==0.
__global__ void __launch_bounds__(256) sgemm_kernel(const float* __restrict__ A,
                                                    const float* __restrict__ B,
                                                    const float* __restrict__ bias,
                                                    float* __restrict__ C,
                                                    int M, int N, int K) {
    __shared__ __align__(16) float As[8][128];
    __shared__ __align__(16) float Bs[8][128];

    int bn = blockIdx.x * 128;
    int bm = blockIdx.y * 128;
    int tid = threadIdx.x;

    int lrow = tid >> 1;          // 0..127
    int lk   = (tid & 1) * 4;     // 0 or 4
    int tx   = tid & 15;          // 0..15
    int ty   = tid >> 4;          // 0..15

    const float* Aptr = A + (size_t)(bm + lrow) * K + lk;
    const float* Bptr = B + (size_t)(bn + lrow) * K + lk;
    bool aval = (bm + lrow) < M;

    float4 av = aval ? *(const float4*)Aptr : make_float4(0.f, 0.f, 0.f, 0.f);
    float4 bv = *(const float4*)Bptr;

    float acc[8][8];
#pragma unroll
    for (int i = 0; i < 8; i++)
#pragma unroll
        for (int j = 0; j < 8; j++) acc[i][j] = 0.f;

    for (int k0 = 0; k0 < K; k0 += 8) {
        As[lk + 0][lrow] = av.x; As[lk + 1][lrow] = av.y;
        As[lk + 2][lrow] = av.z; As[lk + 3][lrow] = av.w;
        Bs[lk + 0][lrow] = bv.x; Bs[lk + 1][lrow] = bv.y;
        Bs[lk + 2][lrow] = bv.z; Bs[lk + 3][lrow] = bv.w;
        __syncthreads();

        if (k0 + 8 < K) {   // prefetch next k-slab into registers
            av = aval ? *(const float4*)(Aptr + k0 + 8) : make_float4(0.f, 0.f, 0.f, 0.f);
            bv = *(const float4*)(Bptr + k0 + 8);
        }

#pragma unroll
        for (int k = 0; k < 8; k++) {
            float ar[8], br[8];
            *(float4*)(ar)     = *(const float4*)&As[k][ty * 8];
            *(float4*)(ar + 4) = *(const float4*)&As[k][ty * 8 + 4];
            *(float4*)(br)     = *(const float4*)&Bs[k][tx * 8];
            *(float4*)(br + 4) = *(const float4*)&Bs[k][tx * 8 + 4];
#pragma unroll
            for (int i = 0; i < 8; i++)
#pragma unroll
                for (int j = 0; j < 8; j++)
                    acc[i][j] = fmaf(ar[i], br[j], acc[i][j]);
        }
        __syncthreads();
    }

    // epilogue
    float4 bb0 = *(const float4*)&bias[bn + tx * 8];
    float4 bb1 = *(const float4*)&bias[bn + tx * 8 + 4];
#pragma unroll
    for (int i = 0; i < 8; i++) {
        int m = bm + ty * 8 + i;
        if (m < M) {
            float4 o0 = make_float4(acc[i][0] + bb0.x, acc[i][1] + bb0.y,
                                    acc[i][2] + bb0.z, acc[i][3] + bb0.w);
            float4 o1 = make_float4(acc[i][4] + bb1.x, acc[i][5] + bb1.y,
                                    acc[i][6] + bb1.z, acc[i][7] + bb1.w);
            *(float4*)&C[(size_t)m * N + bn + tx * 8]     = o0;
            *(float4*)&C[(size_t)m * N + bn + tx * 8 + 4] = o1;
        }
    }
}

// ---------------- recurrence: 64 persistent CTAs, global spin barrier per step ---
// CTA b owns h indices [8b, 8b+8)  -> 32 gate rows {g*512 + 8b + jj}.
// Warp w handles k-chunk [64w, 64w+64); lane l handles local gate row l.
// W_hh slice lives in registers (16 float4 per thread). h broadcast via shfl.
__global__ void __launch_bounds__(256, 1) lstm_kernel(const float* __restrict__ Whh,
                                                      const float* __restrict__ h0,
                                                      const float* __restrict__ c0,
                                                      float* __restrict__ out_tail) {
    int b    = blockIdx.x;
    int w    = threadIdx.x >> 5;
    int lane = threadIdx.x & 31;
    int gate = lane >> 3;
    int jj   = lane & 7;
    int grow  = gate * HID + b * 8 + jj;    // global gate row for this lane
    int kbase = w * 64;

    float4 Wreg[16];
    {
        const float4* wp = (const float4*)(Whh + (size_t)grow * HID + kbase);
#pragma unroll
        for (int i = 0; i < 16; i++) Wreg[i] = wp[i];
    }

    __shared__ float part[8][32];
    float c_val = 0.f;
    if (w == 0 && lane < 8) c_val = c0[b * 8 + lane];

    for (int t = 0; t < T_TOT; t++) {
        const float* hp = t ? (g_hs + (size_t)(t - 1) * HID) : h0;
        // issue X early (independent of h)
        float xv = (w == 0) ? g_X[(size_t)t * G4H + grow] : 0.f;
        float ha = hp[kbase + lane];
        float hb = hp[kbase + 32 + lane];

        float a0 = 0.f, a1 = 0.f, a2 = 0.f, a3 = 0.f;
#pragma unroll
        for (int m = 0; m < 16; m++) {
            float src = (m < 8) ? ha : hb;
            int base = (4 * m) & 31;
            a0 = fmaf(Wreg[m].x, __shfl_sync(0xffffffffu, src, base + 0), a0);
            a1 = fmaf(Wreg[m].y, __shfl_sync(0xffffffffu, src, base + 1), a1);
            a2 = fmaf(Wreg[m].z, __shfl_sync(0xffffffffu, src, base + 2), a2);
            a3 = fmaf(Wreg[m].w, __shfl_sync(0xffffffffu, src, base + 3), a3);
        }
        part[w][lane] = (a0 + a1) + (a2 + a3);
        __syncthreads();

        if (w == 0) {
            float g = xv;
#pragma unroll
            for (int q = 0; q < 8; q++) g += part[q][lane];
            // gather i,f,g,o for output jj (= lane for lanes 0..7)
            float vi = __shfl_sync(0xffffffffu, g, jj);
            float vf = __shfl_sync(0xffffffffu, g, 8 + jj);
            float vg = __shfl_sync(0xffffffffu, g, 16 + jj);
            float vo = __shfl_sync(0xffffffffu, g, 24 + jj);
            if (lane < 8) {
                float fi = 1.f / (1.f + __expf(-vi));
                float ff = 1.f / (1.f + __expf(-vf));
                float fg = tanhf(vg);
                float fo = 1.f / (1.f + __expf(-vo));
                c_val = ff * c_val + fi * fg;
                g_hs[(size_t)t * HID + b * 8 + lane] = fo * tanhf(c_val);
            }
            __threadfence();                    // publish h before arrival
            if (lane == 0) atomicAdd(&g_cnt[t], 1);
        }
        // all warps wait for every CTA's h_t
        if (lane == 0) {
            volatile int* p = &g_cnt[t];
            while (*p < NCTA) {}
        }
        __syncwarp();
        __threadfence();                        // acquire before reading hs[t]
    }

    if (w == 0 && lane < 8) {
        out_tail[b * 8 + lane]       = g_hs[(size_t)SEQLEN * HID + b * 8 + lane];  // hT
        out_tail[HID + b * 8 + lane] = c_val;                                      // cT
    }
}

// ---------------- launch --------------------------------------------------------
extern "C" void kernel_launch(void* const* d_in, const int* in_sizes, int n_in,
                              void* d_out, int out_size) {
    const int*   seq   = (const int*)d_in[0];
    const float* h0    = (const float*)d_in[1];
    const float* c0    = (const float*)d_in[2];
    const float* embt  = (const float*)d_in[3];
    const float* W_ih  = (const float*)d_in[4];
    const float* W_hh  = (const float*)d_in[5];
    const float* b_ih  = (const float*)d_in[6];
    const float* b_hh  = (const float*)d_in[7];
    const float* W_out = (const float*)d_in[8];
    const float* b_out = (const float*)d_in[9];
    float* out = (float*)d_out;

    float *p_emb, *p_bias, *p_X, *p_hs;
    cudaGetSymbolAddress((void**)&p_emb,  g_emb);
    cudaGetSymbolAddress((void**)&p_bias, g_bias);
    cudaGetSymbolAddress((void**)&p_X,    g_X);
    cudaGetSymbolAddress((void**)&p_hs,   g_hs);

    // K0: gather + bias + counter reset
    setup_kernel<<<T_TOT + 8, 256>>>(seq, embt, b_ih, b_hh);

    // K1: X = emb @ W_ih^T + (b_ih+b_hh)   [513 x 2048, K=256]
    {
        dim3 grid(G4H / 128, (T_TOT + 127) / 128);
        sgemm_kernel<<<grid, 256>>>(p_emb, W_ih, p_bias, p_X, T_TOT, G4H, EMB);
    }

    // K2: 513-step recurrence -> g_hs, plus hT/cT tail of d_out
    lstm_kernel<<<NCTA, 256>>>(W_hh, h0, c0, out + (size_t)T_TOT * VOCAB);

    // K3: logits = hs @ W_out^T + b_out    [513 x 32000, K=512] -> d_out
    {
        dim3 grid(VOCAB / 128, (T_TOT + 127) / 128);
        sgemm_kernel<<<grid, 256>>>(p_hs, W_out, b_out, out, T_TOT, VOCAB, HID);
    }
}

// round 2
// speedup vs baseline: 1.2754x; 1.2754x over previous
#include <cuda_runtime.h>

#define SEQLEN  512
#define T_TOT   513      // <SOS> + 512 teacher-forced tokens
#define EMB     256
#define HID     512
#define G4H     2048     // 4*HID
#define VOCAB   32000
#define NCTA    64       // recurrence CTAs (co-resident; 64 <= 148 SMs)
#define SOS_ID  1

// ---------------- scratch (device globals; no allocation allowed) ----------------
__device__ float g_emb[T_TOT * EMB];
__device__ float g_bias[G4H];
__device__ float g_X[T_TOT * G4H];
__device__ float g_hs[T_TOT * HID];
__device__ int   g_cnt[T_TOT];

// ---------------- K0: gather embeddings, combine biases, reset counters ----------
__global__ void setup_kernel(const int* __restrict__ seq,
                             const float* __restrict__ emb_table,
                             const float* __restrict__ b_ih,
                             const float* __restrict__ b_hh) {
    int b = blockIdx.x, t = threadIdx.x;   // blockDim == 256 == EMB
    if (b < T_TOT) {
        int tok = (b == 0) ? SOS_ID : seq[b - 1];
        g_emb[b * EMB + t] = emb_table[tok * EMB + t];
        if (t == 0) g_cnt[b] = 0;
    } else {
        int i = (b - T_TOT) * 256 + t;
        g_bias[i] = b_ih[i] + b_hh[i];
    }
}

// ---------------- FFMA SGEMM (used for K1 only; small) ---------------------------
__global__ void __launch_bounds__(256) sgemm_kernel(const float* __restrict__ A,
                                                    const float* __restrict__ B,
                                                    const float* __restrict__ bias,
                                                    float* __restrict__ C,
                                                    int M, int N, int K) {
    __shared__ __align__(16) float As[8][128];
    __shared__ __align__(16) float Bs[8][128];

    int bn = blockIdx.x * 128;
    int bm = blockIdx.y * 128;
    int tid = threadIdx.x;
    int lrow = tid >> 1;
    int lk   = (tid & 1) * 4;
    int tx   = tid & 15;
    int ty   = tid >> 4;

    const float* Aptr = A + (size_t)(bm + lrow) * K + lk;
    const float* Bptr = B + (size_t)(bn + lrow) * K + lk;
    bool aval = (bm + lrow) < M;

    float4 av = aval ? *(const float4*)Aptr : make_float4(0.f, 0.f, 0.f, 0.f);
    float4 bv = *(const float4*)Bptr;

    float acc[8][8];
#pragma unroll
    for (int i = 0; i < 8; i++)
#pragma unroll
        for (int j = 0; j < 8; j++) acc[i][j] = 0.f;

    for (int k0 = 0; k0 < K; k0 += 8) {
        As[lk + 0][lrow] = av.x; As[lk + 1][lrow] = av.y;
        As[lk + 2][lrow] = av.z; As[lk + 3][lrow] = av.w;
        Bs[lk + 0][lrow] = bv.x; Bs[lk + 1][lrow] = bv.y;
        Bs[lk + 2][lrow] = bv.z; Bs[lk + 3][lrow] = bv.w;
        __syncthreads();

        if (k0 + 8 < K) {
            av = aval ? *(const float4*)(Aptr + k0 + 8) : make_float4(0.f, 0.f, 0.f, 0.f);
            bv = *(const float4*)(Bptr + k0 + 8);
        }

#pragma unroll
        for (int k = 0; k < 8; k++) {
            float ar[8], br[8];
            *(float4*)(ar)     = *(const float4*)&As[k][ty * 8];
            *(float4*)(ar + 4) = *(const float4*)&As[k][ty * 8 + 4];
            *(float4*)(br)     = *(const float4*)&Bs[k][tx * 8];
            *(float4*)(br + 4) = *(const float4*)&Bs[k][tx * 8 + 4];
#pragma unroll
            for (int i = 0; i < 8; i++)
#pragma unroll
                for (int j = 0; j < 8; j++)
                    acc[i][j] = fmaf(ar[i], br[j], acc[i][j]);
        }
        __syncthreads();
    }

    float4 bb0 = *(const float4*)&bias[bn + tx * 8];
    float4 bb1 = *(const float4*)&bias[bn + tx * 8 + 4];
#pragma unroll
    for (int i = 0; i < 8; i++) {
        int m = bm + ty * 8 + i;
        if (m < M) {
            float4 o0 = make_float4(acc[i][0] + bb0.x, acc[i][1] + bb0.y,
                                    acc[i][2] + bb0.z, acc[i][3] + bb0.w);
            float4 o1 = make_float4(acc[i][4] + bb1.x, acc[i][5] + bb1.y,
                                    acc[i][6] + bb1.z, acc[i][7] + bb1.w);
            *(float4*)&C[(size_t)m * N + bn + tx * 8]     = o0;
            *(float4*)&C[(size_t)m * N + bn + tx * 8 + 4] = o1;
        }
    }
}

// ---------------- tf32 tensor-core GEMM (K3): C = A.B^T + bias -------------------
// Split-tf32 (3 MMAs) for ~fp32 accuracy. CTA tile 128x128, warps 2x4 (64x32 each),
// k-chunk 16, cp.async double buffer. A:[M,K] fp32 (ragged M ok), B:[N,K], N%128==0.

__device__ __forceinline__ void cp_async16(unsigned dst, const void* src, int sz) {
    asm volatile("cp.async.ca.shared.global [%0], [%1], 16, %2;\n"
                 :: "r"(dst), "l"(src), "r"(sz));
}
__device__ __forceinline__ void split_tf32(float x, unsigned& hi, unsigned& lo) {
    unsigned h;
    asm("cvt.rna.tf32.f32 %0, %1;" : "=r"(h) : "f"(x));
    float r = x - __uint_as_float(h);
    unsigned l;
    asm("cvt.rna.tf32.f32 %0, %1;" : "=r"(l) : "f"(r));
    hi = h; lo = l;
}
__device__ __forceinline__ void mma8(float* c, const unsigned* a, const unsigned* b) {
    asm volatile("mma.sync.aligned.m16n8k8.row.col.f32.tf32.tf32.f32 "
                 "{%0,%1,%2,%3}, {%4,%5,%6,%7}, {%8,%9}, {%0,%1,%2,%3};"
                 : "+f"(c[0]), "+f"(c[1]), "+f"(c[2]), "+f"(c[3])
                 : "r"(a[0]), "r"(a[1]), "r"(a[2]), "r"(a[3]),
                   "r"(b[0]), "r"(b[1]));
}

__global__ void __launch_bounds__(256) tf32_gemm_kernel(const float* __restrict__ A,
                                                        const float* __restrict__ B,
                                                        const float* __restrict__ bias,
                                                        float* __restrict__ C,
                                                        int M, int N, int K) {
    __shared__ float As[2][128][20];   // 16 k + 4 pad (stride 20: conflict-free frags)
    __shared__ float Bs[2][128][20];

    int bm = blockIdx.x * 128;   // m fastest -> B tile shared across m within a wave
    int bn = blockIdx.y * 128;
    int tid  = threadIdx.x;
    int warp = tid >> 5;
    int wm   = warp >> 2;        // 0..1
    int wn   = warp & 3;         // 0..3
    int lane = tid & 31;
    int group = lane >> 2;       // 0..7
    int tg    = lane & 3;        // 0..3

    const int NC = K / 16;       // k-chunks

    // global->smem (cp.async): 512 16B segments each for A and B; 2 per thread each
    auto load_chunk = [&](int s, int kc) {
#pragma unroll
        for (int i = 0; i < 2; i++) {
            int id  = tid + i * 256;
            int row = id >> 2;
            int kk  = (id & 3) * 4;
            int ar  = bm + row;
            int cr  = ar < M ? ar : (M - 1);
            cp_async16((unsigned)__cvta_generic_to_shared(&As[s][row][kk]),
                       A + (size_t)cr * K + kc + kk, ar < M ? 16 : 0);
            cp_async16((unsigned)__cvta_generic_to_shared(&Bs[s][row][kk]),
                       B + (size_t)(bn + row) * K + kc + kk, 16);
        }
        asm volatile("cp.async.commit_group;\n");
    };

    float acc[4][4][4];
#pragma unroll
    for (int mt = 0; mt < 4; mt++)
#pragma unroll
        for (int nt = 0; nt < 4; nt++)
#pragma unroll
            for (int e = 0; e < 4; e++) acc[mt][nt][e] = 0.f;

    load_chunk(0, 0);

    for (int c = 0; c < NC; c++) {
        if (c + 1 < NC) {
            load_chunk((c + 1) & 1, (c + 1) * 16);
            asm volatile("cp.async.wait_group 1;\n");
        } else {
            asm volatile("cp.async.wait_group 0;\n");
        }
        __syncthreads();

        int s = c & 1;
#pragma unroll
        for (int ks = 0; ks < 2; ks++) {
            int k0 = ks * 8;
            unsigned aH[4][4], aL[4][4], bH[4][2], bL[4][2];
#pragma unroll
            for (int mt = 0; mt < 4; mt++) {
                int r0 = wm * 64 + mt * 16 + group;
#pragma unroll
                for (int e = 0; e < 4; e++) {
                    float v = As[s][r0 + (e & 1) * 8][k0 + tg + (e >> 1) * 4];
                    split_tf32(v, aH[mt][e], aL[mt][e]);
                }
            }
#pragma unroll
            for (int nt = 0; nt < 4; nt++) {
                int n0 = wn * 32 + nt * 8 + group;
#pragma unroll
                for (int e = 0; e < 2; e++) {
                    float v = Bs[s][n0][k0 + tg + e * 4];
                    split_tf32(v, bH[nt][e], bL[nt][e]);
                }
            }
#pragma unroll
            for (int mt = 0; mt < 4; mt++)
#pragma unroll
                for (int nt = 0; nt < 4; nt++) {
                    mma8(acc[mt][nt], aH[mt], bH[nt]);
                    mma8(acc[mt][nt], aL[mt], bH[nt]);
                    mma8(acc[mt][nt], aH[mt], bL[nt]);
                }
        }
        __syncthreads();
    }

    // epilogue
#pragma unroll
    for (int nt = 0; nt < 4; nt++) {
        int col = bn + wn * 32 + nt * 8 + tg * 2;
        float b0 = bias[col], b1 = bias[col + 1];
#pragma unroll
        for (int mt = 0; mt < 4; mt++) {
            int row = bm + wm * 64 + mt * 16 + group;
            if (row < M) {
                float2 o = make_float2(acc[mt][nt][0] + b0, acc[mt][nt][1] + b1);
                *(float2*)&C[(size_t)row * N + col] = o;
            }
            if (row + 8 < M) {
                float2 o = make_float2(acc[mt][nt][2] + b0, acc[mt][nt][3] + b1);
                *(float2*)&C[(size_t)(row + 8) * N + col] = o;
            }
        }
    }
}

// ---------------- recurrence: 64 persistent CTAs, release/acquire barrier --------
__global__ void __launch_bounds__(256, 1) lstm_kernel(const float* __restrict__ Whh,
                                                      const float* __restrict__ h0,
                                                      const float* __restrict__ c0,
                                                      float* __restrict__ out_tail) {
    int b    = blockIdx.x;
    int w    = threadIdx.x >> 5;
    int lane = threadIdx.x & 31;
    int gate = lane >> 3;
    int jj   = lane & 7;
    int grow  = gate * HID + b * 8 + jj;
    int kbase = w * 64;

    float4 Wreg[16];
    {
        const float4* wp = (const float4*)(Whh + (size_t)grow * HID + kbase);
#pragma unroll
        for (int i = 0; i < 16; i++) Wreg[i] = wp[i];
    }

    __shared__ float part[8][32];
    float c_val = 0.f;
    if (w == 0 && lane < 8) c_val = c0[b * 8 + lane];

    for (int t = 0; t < T_TOT; t++) {
        const float* hp = t ? (g_hs + (size_t)(t - 1) * HID) : h0;
        float xv = (w == 0) ? g_X[(size_t)t * G4H + grow] : 0.f;
        float ha = hp[kbase + lane];
        float hb = hp[kbase + 32 + lane];

        float a0 = 0.f, a1 = 0.f, a2 = 0.f, a3 = 0.f;
#pragma unroll
        for (int m = 0; m < 16; m++) {
            float src = (m < 8) ? ha : hb;
            int base = (4 * m) & 31;
            a0 = fmaf(Wreg[m].x, __shfl_sync(0xffffffffu, src, base + 0), a0);
            a1 = fmaf(Wreg[m].y, __shfl_sync(0xffffffffu, src, base + 1), a1);
            a2 = fmaf(Wreg[m].z, __shfl_sync(0xffffffffu, src, base + 2), a2);
            a3 = fmaf(Wreg[m].w, __shfl_sync(0xffffffffu, src, base + 3), a3);
        }
        part[w][lane] = (a0 + a1) + (a2 + a3);
        __syncthreads();

        if (w == 0) {
            float g = xv;
#pragma unroll
            for (int q = 0; q < 8; q++) g += part[q][lane];
            float vi = __shfl_sync(0xffffffffu, g, jj);
            float vf = __shfl_sync(0xffffffffu, g, 8 + jj);
            float vg = __shfl_sync(0xffffffffu, g, 16 + jj);
            float vo = __shfl_sync(0xffffffffu, g, 24 + jj);
            if (lane < 8) {
                float ti = __expf(-vi);
                float tf = __expf(-vf);
                float to = __expf(-vo);
                float tg2 = __expf(-2.f * vg);
                float fi = __fdividef(1.f, 1.f + ti);
                float ff = __fdividef(1.f, 1.f + tf);
                float fo = __fdividef(1.f, 1.f + to);
                float fg = __fdividef(1.f - tg2, 1.f + tg2);
                c_val = ff * c_val + fi * fg;
                float tc = __expf(-2.f * c_val);
                g_hs[(size_t)t * HID + b * 8 + lane] = fo * __fdividef(1.f - tc, 1.f + tc);
            }
            __syncwarp();
            if (lane == 0) {
                asm volatile("red.release.gpu.global.add.s32 [%0], 1;"
                             :: "l"(&g_cnt[t]) : "memory");
            }
        } else if (w == 1 && lane == 0) {
            // single poller per CTA, concurrent with warp0's reduce
            int v;
            do {
                asm volatile("ld.acquire.gpu.global.s32 %0, [%1];"
                             : "=r"(v) : "l"(&g_cnt[t]) : "memory");
            } while (v < NCTA);
        }
        __syncthreads();   // releases CTA; bar provides intra-CTA ordering
    }

    if (w == 0 && lane < 8) {
        out_tail[b * 8 + lane]       = g_hs[(size_t)SEQLEN * HID + b * 8 + lane];
        out_tail[HID + b * 8 + lane] = c_val;
    }
}

// ---------------- launch --------------------------------------------------------
extern "C" void kernel_launch(void* const* d_in, const int* in_sizes, int n_in,
                              void* d_out, int out_size) {
    const int*   seq   = (const int*)d_in[0];
    const float* h0    = (const float*)d_in[1];
    const float* c0    = (const float*)d_in[2];
    const float* embt  = (const float*)d_in[3];
    const float* W_ih  = (const float*)d_in[4];
    const float* W_hh  = (const float*)d_in[5];
    const float* b_ih  = (const float*)d_in[6];
    const float* b_hh  = (const float*)d_in[7];
    const float* W_out = (const float*)d_in[8];
    const float* b_out = (const float*)d_in[9];
    float* out = (float*)d_out;

    float *p_emb, *p_bias, *p_X, *p_hs;
    cudaGetSymbolAddress((void**)&p_emb,  g_emb);
    cudaGetSymbolAddress((void**)&p_bias, g_bias);
    cudaGetSymbolAddress((void**)&p_X,    g_X);
    cudaGetSymbolAddress((void**)&p_hs,   g_hs);

    // K0: gather + bias + counter reset
    setup_kernel<<<T_TOT + 8, 256>>>(seq, embt, b_ih, b_hh);

    // K1: X = emb @ W_ih^T + (b_ih+b_hh)   [513 x 2048, K=256]
    {
        dim3 grid(G4H / 128, (T_TOT + 127) / 128);
        sgemm_kernel<<<grid, 256>>>(p_emb, W_ih, p_bias, p_X, T_TOT, G4H, EMB);
    }

    // K2: 513-step recurrence -> g_hs + hT/cT tail
    lstm_kernel<<<NCTA, 256>>>(W_hh, h0, c0, out + (size_t)T_TOT * VOCAB);

    // K3: logits = hs @ W_out^T + b_out    [513 x 32000, K=512] (tensor cores)
    {
        dim3 grid((T_TOT + 127) / 128, VOCAB / 128);
        tf32_gemm_kernel<<<grid, 256>>>(p_hs, W_out, b_out, out, T_TOT, VOCAB, HID);
    }
}